// round 16
// baseline (speedup 1.0000x reference)
#include <cuda_runtime.h>
#include <cuda_bf16.h>
#include <math.h>

#define Bsz  256
#define Tlen 512
#define IN   512
#define HID  1024
#define OUTD 512
#define G3   (3 * HID)

#define NCTA   128
#define NTHR   256

// ---- persistent-kernel SMEM layout (R13 tiling: 64 n-slices x 2 m-slices) ----
// Wp: [3 gates][64 kt][2 sub][32 lanes] uint4 = 196608 B (16 cols/gate, hi+lo)
// Hs: [8 warps][2 buf][2 var][16 rows][64 B]  = 32768 B  (warp-private chunks)
#define WP_BYTES   196608
#define HS_OFF     WP_BYTES
#define SMEM_BYTES (WP_BYTES + 32768)        // 229376 (proven footprint)

// ---- gemm_x_mma SMEM layout: A [2buf][2var][128r][128B], B same ----
#define XA_VAR   16384
#define XA_BUF   32768
#define XB_OFF   65536
#define XSMEM    131072

// Globals
__device__ float g_xpre[(size_t)Tlen * Bsz * G3];
__device__ float g_h[2][Bsz * HID];
__device__ unsigned short g_hhi[2][Bsz * HID];
__device__ unsigned short g_hlo[2][Bsz * HID];
__device__ unsigned short g_xhi[(size_t)Bsz * Tlen * IN];
__device__ unsigned short g_xlo[(size_t)Bsz * Tlen * IN];
__device__ unsigned short g_wxhi[(size_t)G3 * IN];
__device__ unsigned short g_wxlo[(size_t)G3 * IN];
__device__ float g_bxcat[G3];
__device__ unsigned g_bar;

typedef unsigned int u32;

// ---------------------------------------------------------------------------
__device__ __forceinline__ float sigf(float x) {
    return 1.0f / (1.0f + __expf(-x));
}
__device__ __forceinline__ u32 bfpack(float a, float b) {   // lo half=a, hi half=b
    u32 r;
    asm("cvt.rn.bf16x2.f32 %0, %1, %2;" : "=r"(r) : "f"(b), "f"(a));
    return r;
}
__device__ __forceinline__ void bfsplit(float x, float& hi, float& lo) {
    __nv_bfloat16 h = __float2bfloat16_rn(x);
    hi = __bfloat162float(h);
    lo = x - hi;
}
__device__ __forceinline__ void cpa16(u32 dst, const void* src) {
    asm volatile("cp.async.cg.shared.global [%0], [%1], 16;" :: "r"(dst), "l"(src));
}
__device__ __forceinline__ void ldm_x4(u32* r, u32 addr) {
    asm volatile("ldmatrix.sync.aligned.m8n8.x4.shared.b16 {%0,%1,%2,%3}, [%4];"
                 : "=r"(r[0]), "=r"(r[1]), "=r"(r[2]), "=r"(r[3]) : "r"(addr));
}
__device__ __forceinline__ void mma_bf16(float* d, const u32* a, u32 b0, u32 b1) {
    asm volatile(
        "mma.sync.aligned.m16n8k16.row.col.f32.bf16.bf16.f32 "
        "{%0,%1,%2,%3}, {%4,%5,%6,%7}, {%8,%9}, {%0,%1,%2,%3};"
        : "+f"(d[0]), "+f"(d[1]), "+f"(d[2]), "+f"(d[3])
        : "r"(a[0]), "r"(a[1]), "r"(a[2]), "r"(a[3]), "r"(b0), "r"(b1));
}

// ---------------------------------------------------------------------------
__global__ void zero_h_kernel() {
    int i = blockIdx.x * blockDim.x + threadIdx.x;
    if (i < Bsz * HID) g_h[0][i] = 0.0f;
    if (i < (Bsz * HID) / 2) {
        ((u32*)g_hhi[0])[i] = 0u;
        ((u32*)g_hlo[0])[i] = 0u;
    }
    if (i == 0) g_bar = 0u;
}

// ---------------------------------------------------------------------------
// Prep: split x into bf16 hi/lo (4 floats per thread).
__global__ void split_x_kernel(const float* __restrict__ x) {
    size_t i4 = (size_t)blockIdx.x * blockDim.x + threadIdx.x;
    const size_t n4 = (size_t)Bsz * Tlen * IN / 4;
    if (i4 >= n4) return;
    float4 v = *(const float4*)(x + i4 * 4);
    float h0, l0, h1, l1, h2, l2, h3, l3;
    bfsplit(v.x, h0, l0); bfsplit(v.y, h1, l1);
    bfsplit(v.z, h2, l2); bfsplit(v.w, h3, l3);
    ((u32*)g_xhi)[i4 * 2 + 0] = bfpack(h0, h1);
    ((u32*)g_xhi)[i4 * 2 + 1] = bfpack(h2, h3);
    ((u32*)g_xlo)[i4 * 2 + 0] = bfpack(l0, l1);
    ((u32*)g_xlo)[i4 * 2 + 1] = bfpack(l2, l3);
}

// Prep: split + concatenate Wx gates into [3072][512] hi/lo; concat biases.
__global__ void split_w_kernel(const float* __restrict__ Wxr, const float* __restrict__ Wxc,
                               const float* __restrict__ Wxz,
                               const float* __restrict__ bxr, const float* __restrict__ bxc,
                               const float* __restrict__ bxz) {
    int i4 = blockIdx.x * blockDim.x + threadIdx.x;
    if (i4 < G3 * IN / 4) {
        int n = i4 >> 7;
        int kq = i4 & 127;
        int g = n >> 10, j = n & 1023;
        const float* W = (g == 0) ? Wxr : ((g == 1) ? Wxc : Wxz);
        float4 v = *(const float4*)(W + (size_t)j * IN + kq * 4);
        float h0, l0, h1, l1, h2, l2, h3, l3;
        bfsplit(v.x, h0, l0); bfsplit(v.y, h1, l1);
        bfsplit(v.z, h2, l2); bfsplit(v.w, h3, l3);
        ((u32*)g_wxhi)[i4 * 2 + 0] = bfpack(h0, h1);
        ((u32*)g_wxhi)[i4 * 2 + 1] = bfpack(h2, h3);
        ((u32*)g_wxlo)[i4 * 2 + 0] = bfpack(l0, l1);
        ((u32*)g_wxlo)[i4 * 2 + 1] = bfpack(l2, l3);
    }
    if (i4 < G3) {
        int g = i4 >> 10, j = i4 & 1023;
        g_bxcat[i4] = ((g == 0) ? bxr : ((g == 1) ? bxc : bxz))[j];
    }
}

// ---------------------------------------------------------------------------
// X projection via bf16-split tensor cores. Term-outer MMA ordering for
// accumulator independence (bitwise-identical per-acc accumulation order).
__global__ void __launch_bounds__(NTHR, 1)
gemm_x_mma_kernel() {
    extern __shared__ unsigned char smem[];
    const u32 sb = (u32)__cvta_generic_to_shared(smem);

    const int tid = threadIdx.x;
    const int w = tid >> 5, l = tid & 31;
    const int n0 = blockIdx.x * 128;
    const int m0 = blockIdx.y * 128;
    const int wm = w >> 1, wn = w & 1;

    const int lrow = (l & 7) | (((l >> 3) & 1) << 3);
    const int cb   = (l >> 4) * 16;
    const int lswz = (lrow & 7) * 16;
    const int brow = (l & 7) | ((l >> 4) << 3);
    const int bsg  = ((l >> 3) & 1) * 16;
    const int bswz = (l & 7) * 16;

    const int colp = (l & 3) * 2;
    float2 bias[8];
#pragma unroll
    for (int nt = 0; nt < 8; nt++)
        bias[nt] = *(const float2*)(g_bxcat + n0 + wn * 64 + nt * 8 + colp);

    float acc[2][8][4];
#pragma unroll
    for (int i = 0; i < 2; i++)
#pragma unroll
        for (int j = 0; j < 8; j++)
#pragma unroll
            for (int d = 0; d < 4; d++) acc[i][j][d] = 0.0f;

    auto stage = [&](int kc, int buf) {
#pragma unroll
        for (int p = 0; p < 4; p++) {
            int i = p * NTHR + tid;
            int row = i >> 3, seg = i & 7;
            u32 sw = (u32)((seg ^ (row & 7)) * 16);
            const size_t asrc = (size_t)(m0 + row) * IN + kc * 64 + seg * 8;
            cpa16(sb + buf * XA_BUF + row * 128 + sw, g_xhi + asrc);
            cpa16(sb + buf * XA_BUF + XA_VAR + row * 128 + sw, g_xlo + asrc);
            const size_t bsrc = (size_t)(n0 + row) * IN + kc * 64 + seg * 8;
            cpa16(sb + XB_OFF + buf * XA_BUF + row * 128 + sw, g_wxhi + bsrc);
            cpa16(sb + XB_OFF + buf * XA_BUF + XA_VAR + row * 128 + sw, g_wxlo + bsrc);
        }
    };

    stage(0, 0);
    asm volatile("cp.async.commit_group;");

    for (int kc = 0; kc < 8; kc++) {
        if (kc < 7) {
            stage(kc + 1, (kc + 1) & 1);
            asm volatile("cp.async.commit_group;");
            asm volatile("cp.async.wait_group 1;");
        } else {
            asm volatile("cp.async.wait_group 0;");
        }
        __syncthreads();

        const u32 Ap = sb + (kc & 1) * XA_BUF;
        const u32 Bp = sb + XB_OFF + (kc & 1) * XA_BUF;
#pragma unroll
        for (int ktl = 0; ktl < 4; ktl++) {
            u32 Ahi[2][4], Alo[2][4];
#pragma unroll
            for (int mtl = 0; mtl < 2; mtl++) {
                u32 a = Ap + (wm * 32 + mtl * 16 + lrow) * 128 +
                        (u32)((ktl * 32 + cb) ^ lswz);
                ldm_x4(Ahi[mtl], a);
                ldm_x4(Alo[mtl], a + XA_VAR);
            }
#pragma unroll
            for (int pair = 0; pair < 4; pair++) {
                u32 Bhi[4], Blo[4];
                u32 ba = Bp + (wn * 64 + pair * 16 + brow) * 128 +
                         (u32)((ktl * 32 + bsg) ^ bswz);
                ldm_x4(Bhi, ba);
                ldm_x4(Blo, ba + XA_VAR);
                // term-outer: dependent MMAs on one acc are 4 apart
#pragma unroll
                for (int half = 0; half < 2; half++) {
                    const int nt = pair * 2 + half;
#pragma unroll
                    for (int mtl = 0; mtl < 2; mtl++)
                        mma_bf16(acc[mtl][nt], Ahi[mtl],
                                 Bhi[half * 2], Bhi[half * 2 + 1]);     // hh
                }
#pragma unroll
                for (int half = 0; half < 2; half++) {
                    const int nt = pair * 2 + half;
#pragma unroll
                    for (int mtl = 0; mtl < 2; mtl++)
                        mma_bf16(acc[mtl][nt], Ahi[mtl],
                                 Blo[half * 2], Blo[half * 2 + 1]);     // h*lo
                }
#pragma unroll
                for (int half = 0; half < 2; half++) {
                    const int nt = pair * 2 + half;
#pragma unroll
                    for (int mtl = 0; mtl < 2; mtl++)
                        mma_bf16(acc[mtl][nt], Alo[mtl],
                                 Bhi[half * 2], Bhi[half * 2 + 1]);     // lo*h
                }
            }
        }
        __syncthreads();
    }

#pragma unroll
    for (int mtl = 0; mtl < 2; mtl++) {
        const int r0 = m0 + wm * 32 + mtl * 16 + (l >> 2);
        const int b0 = r0 >> 9, t0 = r0 & (Tlen - 1);
        const int r1 = r0 + 8;
        const int b1 = r1 >> 9, t1 = r1 & (Tlen - 1);
        const size_t base0 = ((size_t)t0 * Bsz + b0) * G3 + n0 + wn * 64 + colp;
        const size_t base1 = ((size_t)t1 * Bsz + b1) * G3 + n0 + wn * 64 + colp;
#pragma unroll
        for (int nt = 0; nt < 8; nt++) {
            float2 o0, o1;
            o0.x = acc[mtl][nt][0] + bias[nt].x;
            o0.y = acc[mtl][nt][1] + bias[nt].y;
            o1.x = acc[mtl][nt][2] + bias[nt].x;
            o1.y = acc[mtl][nt][3] + bias[nt].y;
            *(float2*)(g_xpre + base0 + nt * 8) = o0;
            *(float2*)(g_xpre + base1 + nt * 8) = o1;
        }
    }
}

// ---------------------------------------------------------------------------
// Persistent GRU recurrence (R13 structure, proven): grid (64 n, 2 m),
// warp-private cp.async staging, term-outer MMA ordering (6-wide independence).
__global__ void __launch_bounds__(NTHR, 1)
gru_persistent_kernel(const float* __restrict__ Whr, const float* __restrict__ bhr,
                      const float* __restrict__ Whc, const float* __restrict__ bhc,
                      const float* __restrict__ Whz, const float* __restrict__ bhz) {
    extern __shared__ unsigned char smem[];
    uint4* Wp = (uint4*)smem;
    const u32 sb = (u32)__cvta_generic_to_shared(smem);

    const int tid = threadIdx.x;
    const int w   = tid >> 5;
    const int l   = tid & 31;
    const int nsl = blockIdx.x;            // 0..63
    const int m0  = blockIdx.y * 128;      // 0 or 128
    const int nb0 = nsl * 16;              // per-gate column base

    // ---- Pack weight B-fragments once: Wp[g][kt][sub][lane] = {hi0,hi1,lo0,lo1}
    {
        const float* __restrict__ Wg[3] = {Whr, Whc, Whz};
        for (int e = tid; e < 3 * 64 * 2 * 32; e += NTHR) {
            int g = e >> 12, rem = e & 4095;
            int kt = rem >> 6;
            int sub = (rem >> 5) & 1;
            int lane = rem & 31;
            int n  = nb0 + sub * 8 + (lane >> 2);
            int k0 = kt * 16 + (lane & 3) * 2;
            const float* wr = Wg[g] + (size_t)n * HID + k0;
            float2 wa = *(const float2*)wr;
            float2 wb = *(const float2*)(wr + 8);
            float h0, l0, h1, l1, h8, l8, h9, l9;
            bfsplit(wa.x, h0, l0); bfsplit(wa.y, h1, l1);
            bfsplit(wb.x, h8, l8); bfsplit(wb.y, h9, l9);
            Wp[e] = make_uint4(bfpack(h0, h1), bfpack(h8, h9),
                               bfpack(l0, l1), bfpack(l8, l9));
        }
    }

    // ---- per-lane constants ----
    float2 bR[2], bC[2], bZ[2];
#pragma unroll
    for (int sub = 0; sub < 2; sub++) {
        int col = nb0 + sub * 8 + (l & 3) * 2;
        bR[sub] = *(const float2*)(bhr + col);
        bC[sub] = *(const float2*)(bhc + col);
        bZ[sub] = *(const float2*)(bhz + col);
    }

    const int lrow = (l & 7) | (((l >> 3) & 1) << 3);  // row within 16
    const int cbh  = l >> 4;                           // 16-B half 0/1
    const u32 hsbase = sb + HS_OFF + w * 4096;         // warp-private region

    const int R0 = m0 + w * 16 + (l >> 2);

    __syncthreads();

    for (int t = 0; t < Tlen; t++) {
        const int hb = t & 1, nb = hb ^ 1;

        // ---- prefetch epilogue operands (longest latency) ----
        float2 pxr[2][2], pxc[2][2], pxz[2][2], pho[2][2];
#pragma unroll
        for (int q = 0; q < 2; q++) {
            const int row = R0 + 8 * q;
            const size_t base = ((size_t)t * Bsz + row) * G3;
#pragma unroll
            for (int sub = 0; sub < 2; sub++) {
                const int col = nb0 + sub * 8 + (l & 3) * 2;
                pxr[q][sub] = *(const float2*)(g_xpre + base + col);
                pxc[q][sub] = *(const float2*)(g_xpre + base + HID + col);
                pxz[q][sub] = *(const float2*)(g_xpre + base + 2 * HID + col);
                pho[q][sub] = *(const float2*)(g_h[hb] + (size_t)row * HID + col);
            }
        }

        // warp-private staging: 16 rows x 32 k x 2 var per chunk (2 KB)
        const unsigned short* __restrict__ srcs[2] = {g_hhi[hb], g_hlo[hb]};
        auto stage = [&](int kc, int buf) {
#pragma unroll
            for (int j = 0; j < 4; j++) {
                int idx = j * 32 + l;                // 0..127
                int var = idx >> 6, rem = idx & 63;
                int row = rem >> 2, seg = rem & 3;
                const void* src = srcs[var] +
                    (size_t)(m0 + w * 16 + row) * HID + kc * 32 + seg * 8;
                u32 dst = hsbase + buf * 2048 + var * 1024 + row * 64 +
                          ((seg ^ ((row >> 1) & 3)) * 16);
                cpa16(dst, src);
            }
        };

        float acc[3][2][4];
#pragma unroll
        for (int g = 0; g < 3; g++)
#pragma unroll
            for (int s = 0; s < 2; s++)
#pragma unroll
                for (int d = 0; d < 4; d++) acc[g][s][d] = 0.0f;

        stage(0, 0);
        asm volatile("cp.async.commit_group;");
        stage(1, 1);
        asm volatile("cp.async.commit_group;");

        for (int kc = 0; kc < 32; kc++) {
            if (kc < 31) {
                asm volatile("cp.async.wait_group 1;");
            } else {
                asm volatile("cp.async.wait_group 0;");
            }
            __syncwarp();

            const u32 bufb = hsbase + (kc & 1) * 2048;
#pragma unroll
            for (int ktl = 0; ktl < 2; ktl++) {
                const int kt = kc * 2 + ktl;
                const int ps = ((ktl * 2 + cbh) ^ ((lrow >> 1) & 3)) * 16;
                u32 Ahi[4], Alo[4];
                ldm_x4(Ahi, bufb + lrow * 64 + ps);
                ldm_x4(Alo, bufb + 1024 + lrow * 64 + ps);

                uint4 B[3][2];
#pragma unroll
                for (int g = 0; g < 3; g++)
#pragma unroll
                    for (int sub = 0; sub < 2; sub++)
                        B[g][sub] = Wp[g * 4096 + kt * 64 + sub * 32 + l];

                // term-outer: dependent MMAs on one acc are 6 apart
#pragma unroll
                for (int g = 0; g < 3; g++)
#pragma unroll
                    for (int sub = 0; sub < 2; sub++)
                        mma_bf16(acc[g][sub], Ahi, B[g][sub].x, B[g][sub].y); // hh
#pragma unroll
                for (int g = 0; g < 3; g++)
#pragma unroll
                    for (int sub = 0; sub < 2; sub++)
                        mma_bf16(acc[g][sub], Ahi, B[g][sub].z, B[g][sub].w); // h*loW
#pragma unroll
                for (int g = 0; g < 3; g++)
#pragma unroll
                    for (int sub = 0; sub < 2; sub++)
                        mma_bf16(acc[g][sub], Alo, B[g][sub].x, B[g][sub].y); // loh*W
            }

            if (kc < 30) {
                stage(kc + 2, kc & 1);
                asm volatile("cp.async.commit_group;");
            }
        }

        // ---- fused GRU elementwise update: 2 rows x 2 subs x 2 cols ----
#pragma unroll
        for (int q = 0; q < 2; q++) {
            const int row = R0 + 8 * q;
            const int d0 = q * 2;
#pragma unroll
            for (int sub = 0; sub < 2; sub++) {
                const int col = nb0 + sub * 8 + (l & 3) * 2;
                float aR0 = acc[0][sub][d0], aR1 = acc[0][sub][d0 + 1];
                float aC0 = acc[1][sub][d0], aC1 = acc[1][sub][d0 + 1];
                float aZ0 = acc[2][sub][d0], aZ1 = acc[2][sub][d0 + 1];

                float r0 = sigf(pxr[q][sub].x + aR0 + bR[sub].x);
                float r1 = sigf(pxr[q][sub].y + aR1 + bR[sub].y);
                float c0 = tanhf(pxc[q][sub].x + r0 * (aC0 + bC[sub].x));
                float c1 = tanhf(pxc[q][sub].y + r1 * (aC1 + bC[sub].y));
                float z0 = sigf(pxz[q][sub].x + aZ0 + bZ[sub].x);
                float z1 = sigf(pxz[q][sub].y + aZ1 + bZ[sub].y);
                float hn0 = (1.0f - z0) * pho[q][sub].x + z0 * c0;
                float hn1 = (1.0f - z1) * pho[q][sub].y + z1 * c1;

                const size_t off = (size_t)row * HID + col;
                float2 hv; hv.x = hn0; hv.y = hn1;
                *(float2*)(g_h[nb] + off) = hv;

                float h0f, l0f, h1f, l1f;
                bfsplit(hn0, h0f, l0f);
                bfsplit(hn1, h1f, l1f);
                ((u32*)g_hhi[nb])[off >> 1] = bfpack(h0f, h1f);
                ((u32*)g_hlo[nb])[off >> 1] = bfpack(l0f, l1f);
            }
        }

        // ---- grid barrier (monotonic counter; zeroed in-stream each launch) ----
        __syncthreads();
        if (tid == 0) {
            __threadfence();
            atomicAdd(&g_bar, 1u);
            const unsigned target = (unsigned)(t + 1) * (unsigned)NCTA;
            volatile unsigned* vb = &g_bar;
            while (*vb < target) __nanosleep(64);
            __threadfence();
        }
        __syncthreads();
    }
}

// ---------------------------------------------------------------------------
__global__ void gemm_out_kernel(const float* __restrict__ Wo, const float* __restrict__ bo,
                                float* __restrict__ out) {
    const int BKo = 32;
    __shared__ float HsO[BKo][32];
    __shared__ float WsO[BKo][64];

    const float* __restrict__ h = g_h[0];
    const int n0 = blockIdx.x * 64;
    const int m0 = blockIdx.y * 32;
    const int tid = threadIdx.x;

    const int hr = tid >> 2;
    const int hq = (tid & 3) * 8;
    const int wr = tid >> 1;
    const int wq = (tid & 1) * 16;
    const int tm = tid >> 4;
    const int tn = tid & 15;

    float acc[4][4];
#pragma unroll
    for (int i = 0; i < 4; i++)
#pragma unroll
        for (int j = 0; j < 4; j++) acc[i][j] = 0.f;

    for (int k0 = 0; k0 < HID; k0 += BKo) {
        {
            const float* hp = h + (size_t)(m0 + hr) * HID + k0 + hq;
            float4 h0 = *(const float4*)hp;
            float4 h1 = *(const float4*)(hp + 4);
            HsO[hq + 0][hr] = h0.x; HsO[hq + 1][hr] = h0.y;
            HsO[hq + 2][hr] = h0.z; HsO[hq + 3][hr] = h0.w;
            HsO[hq + 4][hr] = h1.x; HsO[hq + 5][hr] = h1.y;
            HsO[hq + 6][hr] = h1.z; HsO[hq + 7][hr] = h1.w;
        }
        {
            const float* wp = Wo + (size_t)(n0 + wr) * HID + k0 + wq;
#pragma unroll
            for (int u = 0; u < 4; u++) {
                float4 wv = *(const float4*)(wp + u * 4);
                WsO[wq + u * 4 + 0][wr] = wv.x;
                WsO[wq + u * 4 + 1][wr] = wv.y;
                WsO[wq + u * 4 + 2][wr] = wv.z;
                WsO[wq + u * 4 + 3][wr] = wv.w;
            }
        }
        __syncthreads();

#pragma unroll
        for (int k = 0; k < BKo; k++) {
            float4 hv = *(const float4*)&HsO[k][tm * 4];
            float4 wv = *(const float4*)&WsO[k][tn * 4];
            float h4[4] = {hv.x, hv.y, hv.z, hv.w};
            float w4[4] = {wv.x, wv.y, wv.z, wv.w};
#pragma unroll
            for (int i = 0; i < 4; i++)
#pragma unroll
                for (int j = 0; j < 4; j++)
                    acc[i][j] = fmaf(h4[i], w4[j], acc[i][j]);
        }
        __syncthreads();
    }

#pragma unroll
    for (int i = 0; i < 4; i++) {
        const int b = m0 + tm * 4 + i;
#pragma unroll
        for (int j = 0; j < 4; j++) {
            const int o = n0 + tn * 4 + j;
            out[(size_t)b * OUTD + o] = acc[i][j] + bo[o];
        }
    }
}

// ---------------------------------------------------------------------------
extern "C" void kernel_launch(void* const* d_in, const int* in_sizes, int n_in,
                              void* d_out, int out_size) {
    const float* x   = (const float*)d_in[0];
    const float* Wxr = (const float*)d_in[1];
    const float* bxr = (const float*)d_in[2];
    const float* Whr = (const float*)d_in[3];
    const float* bhr = (const float*)d_in[4];
    const float* Wxc = (const float*)d_in[5];
    const float* bxc = (const float*)d_in[6];
    const float* Whc = (const float*)d_in[7];
    const float* bhc = (const float*)d_in[8];
    const float* Wxz = (const float*)d_in[9];
    const float* bxz = (const float*)d_in[10];
    const float* Whz = (const float*)d_in[11];
    const float* bhz = (const float*)d_in[12];
    const float* Wo  = (const float*)d_in[13];
    const float* bo  = (const float*)d_in[14];
    float* out = (float*)d_out;

    cudaFuncSetAttribute(gru_persistent_kernel,
                         cudaFuncAttributeMaxDynamicSharedMemorySize, SMEM_BYTES);
    cudaFuncSetAttribute(gemm_x_mma_kernel,
                         cudaFuncAttributeMaxDynamicSharedMemorySize, XSMEM);

    zero_h_kernel<<<(Bsz * HID + 255) / 256, 256>>>();
    split_x_kernel<<<(int)(((size_t)Bsz * Tlen * IN / 4 + 255) / 256), 256>>>(x);
    split_w_kernel<<<(G3 * IN / 4 + 255) / 256, 256>>>(Wxr, Wxc, Wxz, bxr, bxc, bxz);
    gemm_x_mma_kernel<<<dim3(G3 / 128, (Bsz * Tlen) / 128), NTHR, XSMEM>>>();
    gru_persistent_kernel<<<dim3(64, 2), NTHR, SMEM_BYTES>>>(Whr, bhr, Whc, bhc, Whz, bhz);
    gemm_out_kernel<<<dim3(OUTD / 64, Bsz / 32), 128>>>(Wo, bo, out);
}